// round 1
// baseline (speedup 1.0000x reference)
#include <cuda_runtime.h>

#define N_TOK 343
#define EMBED 192
#define HEADS 6
#define HD 32
#define BATCH 256
#define NWIN 64
#define QSCALE 0.17677669529663687f  /* 32^-0.5 */

#define M_ROWS (BATCH * N_TOK)        /* 87808 = 1372*64 */
#define SMEM_ATTN (2 * 344 * 32 * 4)  /* K + V tiles, padded to 344 rows */

// ---------------- scratch (device globals: no allocations allowed) ----------
__device__ float g_q[BATCH * HEADS * N_TOK * HD];     // [b,h,n,d]
__device__ float g_k[BATCH * HEADS * N_TOK * HD];
__device__ float g_v[BATCH * HEADS * N_TOK * HD];
__device__ float g_ctx[BATCH * N_TOK * EMBED];        // [b,n,c]
__device__ float g_bias[HEADS * N_TOK * N_TOK];       // [h,q,k]

// ---------------- bias gather: bias[h,q,k] = table[rel_idx[q,k], h] --------
__global__ void bias_gather_kernel(const float* __restrict__ table,
                                   const int* __restrict__ rel) {
    int i = blockIdx.x * blockDim.x + threadIdx.x;
    if (i >= N_TOK * N_TOK) return;
    int r = rel[i];
#pragma unroll
    for (int h = 0; h < HEADS; ++h)
        g_bias[h * N_TOK * N_TOK + i] = table[r * HEADS + h];
}

// ---------------- shared GEMM core: C[m,n] = sum_k A[m,k]*W[n,k] ------------
// BM=BN=64, BK=32, 256 threads, 4x4 per thread. K=192 (6 chunks), exact tiles.
__device__ __forceinline__ void gemm_core(const float* __restrict__ A,
                                          const float* __restrict__ W,
                                          int m0, int n0, int tid,
                                          float* As, float* Bs,
                                          float acc[4][4]) {
    const int tx = tid & 15, ty = tid >> 4;
#pragma unroll 1
    for (int kt = 0; kt < 6; ++kt) {
        const int k0 = kt * 32;
#pragma unroll
        for (int r = 0; r < 2; ++r) {
            int idx = tid + 256 * r;
            int row = idx >> 3, c4 = idx & 7;
            float4 av = *(const float4*)(A + (size_t)(m0 + row) * EMBED + k0 + c4 * 4);
            float4 wv = *(const float4*)(W + (size_t)(n0 + row) * EMBED + k0 + c4 * 4);
            int kb = c4 * 4;
            As[(kb + 0) * 68 + row] = av.x;
            As[(kb + 1) * 68 + row] = av.y;
            As[(kb + 2) * 68 + row] = av.z;
            As[(kb + 3) * 68 + row] = av.w;
            Bs[(kb + 0) * 68 + row] = wv.x;
            Bs[(kb + 1) * 68 + row] = wv.y;
            Bs[(kb + 2) * 68 + row] = wv.z;
            Bs[(kb + 3) * 68 + row] = wv.w;
        }
        __syncthreads();
#pragma unroll
        for (int kk = 0; kk < 32; ++kk) {
            float4 a4 = *(const float4*)(As + kk * 68 + ty * 4);
            float4 b4 = *(const float4*)(Bs + kk * 68 + tx * 4);
            float a[4] = {a4.x, a4.y, a4.z, a4.w};
            float b[4] = {b4.x, b4.y, b4.z, b4.w};
#pragma unroll
            for (int i = 0; i < 4; ++i)
#pragma unroll
                for (int j = 0; j < 4; ++j)
                    acc[i][j] += a[i] * b[j];
        }
        __syncthreads();
    }
}

// ---------------- fused Q + KV projections ----------------------------------
// grid.y in [0,9): y<3 -> Q (x_in @ q_w^T * scale), else KV (x_cross @ kv_w^T)
__global__ __launch_bounds__(256) void gemm_qkv_kernel(
    const float* __restrict__ x_in, const float* __restrict__ x_cross,
    const float* __restrict__ q_w, const float* __restrict__ kv_w) {
    __shared__ float As[32 * 68];
    __shared__ float Bs[32 * 68];
    const int tid = threadIdx.x;
    const int m0 = blockIdx.x * 64;
    const int yt = blockIdx.y;
    const bool isq = (yt < 3);
    const float* A = isq ? x_in : x_cross;
    const float* W = isq ? q_w : kv_w;
    const int n0 = isq ? yt * 64 : (yt - 3) * 64;

    float acc[4][4];
#pragma unroll
    for (int i = 0; i < 4; ++i)
#pragma unroll
        for (int j = 0; j < 4; ++j) acc[i][j] = 0.f;

    gemm_core(A, W, m0, n0, tid, As, Bs, acc);

    const int tx = tid & 15, ty = tid >> 4;
#pragma unroll
    for (int i = 0; i < 4; ++i) {
        int m = m0 + ty * 4 + i;
        int bb = m / N_TOK;
        int nn = m - bb * N_TOK;
#pragma unroll
        for (int j = 0; j < 4; ++j) {
            int n = n0 + tx * 4 + j;
            float v = acc[i][j];
            if (isq) {
                int h = n >> 5, d = n & 31;
                g_q[((size_t)(bb * HEADS + h) * N_TOK + nn) * HD + d] = v * QSCALE;
            } else {
                int nc = (n < EMBED) ? n : n - EMBED;
                float* dst = (n < EMBED) ? g_k : g_v;
                int h = nc >> 5, d = nc & 31;
                dst[((size_t)(bb * HEADS + h) * N_TOK + nn) * HD + d] = v;
            }
        }
    }
}

// ---------------- output projection: out = ctx @ proj_w^T + proj_b ---------
__global__ __launch_bounds__(256) void gemm_proj_kernel(
    const float* __restrict__ proj_w, const float* __restrict__ proj_b,
    float* __restrict__ out) {
    __shared__ float As[32 * 68];
    __shared__ float Bs[32 * 68];
    const int tid = threadIdx.x;
    const int m0 = blockIdx.x * 64;
    const int n0 = blockIdx.y * 64;

    float acc[4][4];
#pragma unroll
    for (int i = 0; i < 4; ++i)
#pragma unroll
        for (int j = 0; j < 4; ++j) acc[i][j] = 0.f;

    gemm_core(g_ctx, proj_w, m0, n0, tid, As, Bs, acc);

    const int tx = tid & 15, ty = tid >> 4;
#pragma unroll
    for (int i = 0; i < 4; ++i) {
        int m = m0 + ty * 4 + i;
#pragma unroll
        for (int j = 0; j < 4; ++j) {
            int n = n0 + tx * 4 + j;
            out[(size_t)m * EMBED + n] = acc[i][j] + proj_b[n];
        }
    }
}

// ---------------- flash attention per (b, h) --------------------------------
// 352 threads; one thread per q-row; K,V [344x32] in dynamic smem (row 343=0).
// Online softmax, chunk=8, rescale amortized per chunk.
__global__ __launch_bounds__(352) void attn_kernel(const float* __restrict__ mask) {
    extern __shared__ float sm[];
    float* Ks = sm;             // 344*32
    float* Vs = sm + 344 * 32;  // 344*32
    const int bh = blockIdx.x;
    const int b = bh / HEADS;
    const int h = bh - b * HEADS;
    const int w = b & (NWIN - 1);
    const int tid = threadIdx.x;

    const float4* Ksrc = (const float4*)(g_k + (size_t)bh * N_TOK * HD);
    const float4* Vsrc = (const float4*)(g_v + (size_t)bh * N_TOK * HD);
    float4* Kd = (float4*)Ks;
    float4* Vd = (float4*)Vs;
    const float4 z4 = make_float4(0.f, 0.f, 0.f, 0.f);
    for (int i = tid; i < 344 * 8; i += 352) {
        Kd[i] = (i < N_TOK * 8) ? Ksrc[i] : z4;
        Vd[i] = (i < N_TOK * 8) ? Vsrc[i] : z4;
    }
    __syncthreads();

    const int q = tid;
    if (q < N_TOK) {
        float4 qv[8];
        const float4* qsrc = (const float4*)(g_q + ((size_t)bh * N_TOK + q) * HD);
#pragma unroll
        for (int c = 0; c < 8; ++c) qv[c] = qsrc[c];

        const float* brow = g_bias + ((size_t)h * N_TOK + q) * N_TOK;
        const float* mrow = mask + ((size_t)w * N_TOK + q) * N_TOK;

        float mrun = -1e30f, l = 0.f;
        float4 accv[8];
#pragma unroll
        for (int c = 0; c < 8; ++c) accv[c] = z4;

#pragma unroll 1
        for (int k0 = 0; k0 < N_TOK; k0 += 8) {
            float s[8];
#pragma unroll
            for (int j = 0; j < 8; ++j) {
                int k = k0 + j;
                float sj = 0.f;
#pragma unroll
                for (int c = 0; c < 8; ++c) {
                    float4 kv = Kd[k * 8 + c];
                    sj += qv[c].x * kv.x + qv[c].y * kv.y +
                          qv[c].z * kv.z + qv[c].w * kv.w;
                }
                if (k < N_TOK) s[j] = sj + brow[k] + mrow[k];
                else           s[j] = -1e30f;
            }
            float mc = s[0];
#pragma unroll
            for (int j = 1; j < 8; ++j) mc = fmaxf(mc, s[j]);
            float newm = fmaxf(mrun, mc);
            float alpha = __expf(mrun - newm);
            l *= alpha;
#pragma unroll
            for (int c = 0; c < 8; ++c) {
                accv[c].x *= alpha; accv[c].y *= alpha;
                accv[c].z *= alpha; accv[c].w *= alpha;
            }
#pragma unroll
            for (int j = 0; j < 8; ++j) {
                float p = __expf(s[j] - newm);
                l += p;
#pragma unroll
                for (int c = 0; c < 8; ++c) {
                    float4 vv = Vd[(k0 + j) * 8 + c];
                    accv[c].x += p * vv.x; accv[c].y += p * vv.y;
                    accv[c].z += p * vv.z; accv[c].w += p * vv.w;
                }
            }
            mrun = newm;
        }

        float inv = __fdividef(1.f, l);
        float4* dst = (float4*)(g_ctx + ((size_t)(b * N_TOK + q)) * EMBED + h * HD);
#pragma unroll
        for (int c = 0; c < 8; ++c) {
            float4 o = accv[c];
            o.x *= inv; o.y *= inv; o.z *= inv; o.w *= inv;
            dst[c] = o;
        }
    }
}

// ---------------- launch -----------------------------------------------------
extern "C" void kernel_launch(void* const* d_in, const int* in_sizes, int n_in,
                              void* d_out, int out_size) {
    const float* x_in    = (const float*)d_in[0];
    const float* x_cross = (const float*)d_in[1];
    const float* mask    = (const float*)d_in[2];
    const float* q_w     = (const float*)d_in[3];
    const float* kv_w    = (const float*)d_in[4];
    const float* proj_w  = (const float*)d_in[5];
    const float* proj_b  = (const float*)d_in[6];
    const float* table   = (const float*)d_in[7];
    const int*   rel     = (const int*)d_in[8];
    float* out = (float*)d_out;

    cudaFuncSetAttribute(attn_kernel,
                         cudaFuncAttributeMaxDynamicSharedMemorySize, SMEM_ATTN);

    bias_gather_kernel<<<(N_TOK * N_TOK + 255) / 256, 256>>>(table, rel);
    gemm_qkv_kernel<<<dim3(M_ROWS / 64, 9), 256>>>(x_in, x_cross, q_w, kv_w);
    attn_kernel<<<BATCH * HEADS, 352, SMEM_ATTN>>>(mask);
    gemm_proj_kernel<<<dim3(M_ROWS / 64, 3), 256>>>(proj_w, proj_b, out);
}